// round 2
// baseline (speedup 1.0000x reference)
#include <cuda_runtime.h>

// ---------------------------------------------------------------------------
// BoxCrossCategoryLoss: loss = sum over 36 recipe terms of relu(pA + pB - C)
// where p's are log-probabilities built from log1mexp combinations.
// Strategy: compute in log2 domain (ex2/lg2 MUFU only), algebraically fuse
// the NEG-recipe log1mexp(pAC) terms into direct lg2(1 - product) forms.
// The 3 int rel_id inputs are never read (dead in the reference).
// ---------------------------------------------------------------------------

#define GRID_BLOCKS 1216
#define NTHREADS 256

__device__ float g_partials[GRID_BLOCKS];

__device__ __forceinline__ float ex2f_(float x) {
    float r; asm("ex2.approx.f32 %0, %1;" : "=f"(r) : "f"(x)); return r;
}
__device__ __forceinline__ float lg2f_(float x) {
    float r; asm("lg2.approx.f32 %0, %1;" : "=f"(r) : "f"(x)); return r;
}
// log2(1 - 2^x)  for x < 0 (x in log2 units)
__device__ __forceinline__ float l1m2(float x) {
    return lg2f_(1.0f - ex2f_(x));
}

// Per-element loss in log2 units. All 12 inputs are natural-log values
// pre-scaled by log2(e).
__device__ __forceinline__ float elem_loss(
    float ab0, float ab1, float ba0, float ba1,
    float bc0, float bc1, float cb0, float cb1,
    float ac0, float ac1, float ca0, float ca1)
{
    // --- AB pair (v1 = vol_AB, v2 = vol_BA) ---
    float ABla0 = l1m2(ab0), ABlb0 = l1m2(ba0);
    float ABla1 = l1m2(ab1), ABlb1 = l1m2(ba1);
    float AB0c0 = ab0 + ABlb0;              // PC col0
    float AB1c0 = ABla0 + ba0;              // CP col0
    float AB2c0 = ab0 + ba0;                // CR col0
    float AB0c1 = ab1 + ABlb1;
    float AB1c1 = ABla1 + ba1;
    float AB2c1 = ab1 + ba1;
    float AB3c1 = ABla1 + ABlb1;            // NR col1

    // --- BC pair ---
    float BCla0 = l1m2(bc0), BClb0 = l1m2(cb0);
    float BCla1 = l1m2(bc1), BClb1 = l1m2(cb1);
    float BC0c0 = bc0 + BClb0;
    float BC1c0 = BCla0 + cb0;
    float BC2c0 = bc0 + cb0;
    float BC0c1 = bc1 + BClb1;
    float BC1c1 = BCla1 + cb1;
    float BC2c1 = bc1 + cb1;
    float BC3c1 = BCla1 + BClb1;

    // --- AC pair, column 1 (used directly in LOSS_RECIPE) ---
    float ACla1 = l1m2(ac1), AClb1 = l1m2(ca1);
    float AC0 = ac1 + AClb1;
    float AC1 = ACla1 + ca1;
    float AC2 = ac1 + ca1;
    float AC3 = ACla1 + AClb1;

    // --- AC pair, column 0: only log1mexp(pAC[k][:,0]) is ever needed ---
    // exp(PC)=ua(1-ub), exp(CP)=(1-ua)ub, exp(CR)=ua*ub
    float ua = ex2f_(ac0);
    float ub = ex2f_(ca0);
    float w  = ua * ub;
    float L0 = lg2f_((1.0f - ua) + w);            // log2(1 - ua(1-ub))
    float L1 = lg2f_((1.0f - ub) + w);            // log2(1 - (1-ua)ub)
    float L2 = lg2f_(__fmaf_rn(-ua, ub, 1.0f));   // log2(1 - ua*ub)

    float acc = 0.0f;
#define RTERM(S, X) acc += fmaxf((S) - (X), 0.0f);

    float S1  = AB0c0 + BC0c1;  RTERM(S1,  AC0) RTERM(S1,  L1) RTERM(S1,  L2)
    float S2  = AB0c0 + BC2c1;  RTERM(S2,  AC0) RTERM(S2,  L1) RTERM(S2,  L2)
    float S3  = AB1c0 + BC1c1;  RTERM(S3,  AC1) RTERM(S3,  L0) RTERM(S3,  L2)
    float S4  = AB1c0 + BC2c1;  RTERM(S4,  AC1) RTERM(S4,  L0) RTERM(S4,  L2)
    float S5  = AB2c0 + BC0c1;  RTERM(S5,  AC0) RTERM(S5,  L1) RTERM(S5,  L2)
    float S6  = AB2c0 + BC1c1;  RTERM(S6,  AC1) RTERM(S6,  L0) RTERM(S6,  L2)
    float S7  = AB2c0 + BC2c1;  RTERM(S7,  AC2)
    float S8  = AB2c0 + BC3c1;  RTERM(S8,  AC3) RTERM(S8,  L2)
    float S9  = AB0c1 + BC0c0;  RTERM(S9,  AC0) RTERM(S9,  L1) RTERM(S9,  L2)
    float S10 = AB0c1 + BC2c0;  RTERM(S10, AC0) RTERM(S10, L1) RTERM(S10, L2)
    float S11 = AB1c1 + BC1c0;  RTERM(S11, AC1) RTERM(S11, L0) RTERM(S11, L2)
    float S12 = AB1c1 + BC2c0;  RTERM(S12, AC1) RTERM(S12, L0) RTERM(S12, L2)
    float S13 = AB2c1 + BC2c0;  RTERM(S13, AC2)
    float S14 = AB3c1 + BC2c0;  RTERM(S14, AC3) RTERM(S14, L2)
#undef RTERM
    return acc;
}

__global__ void __launch_bounds__(NTHREADS)
loss_main_kernel(const float* __restrict__ AB, const float* __restrict__ BA,
                 const float* __restrict__ BC, const float* __restrict__ CB,
                 const float* __restrict__ AC, const float* __restrict__ CA,
                 int n_elems)
{
    constexpr float K = 1.44269504088896340736f;  // log2(e)
    const float4* AB4 = (const float4*)AB;
    const float4* BA4 = (const float4*)BA;
    const float4* BC4 = (const float4*)BC;
    const float4* CB4 = (const float4*)CB;
    const float4* AC4 = (const float4*)AC;
    const float4* CA4 = (const float4*)CA;

    int n4 = n_elems >> 1;  // each float4 covers 2 elements (2 cols each)
    float acc = 0.0f;

    for (int j = blockIdx.x * NTHREADS + threadIdx.x; j < n4;
         j += GRID_BLOCKS * NTHREADS) {
        float4 vab = AB4[j], vba = BA4[j];
        float4 vbc = BC4[j], vcb = CB4[j];
        float4 vac = AC4[j], vca = CA4[j];

        acc += elem_loss(vab.x * K, vab.y * K, vba.x * K, vba.y * K,
                         vbc.x * K, vbc.y * K, vcb.x * K, vcb.y * K,
                         vac.x * K, vac.y * K, vca.x * K, vca.y * K);
        acc += elem_loss(vab.z * K, vab.w * K, vba.z * K, vba.w * K,
                         vbc.z * K, vbc.w * K, vcb.z * K, vcb.w * K,
                         vac.z * K, vac.w * K, vca.z * K, vca.w * K);
    }

    // odd tail element (not hit for N = 8M, kept for generality)
    if ((n_elems & 1) && blockIdx.x == 0 && threadIdx.x == 0) {
        int i = n_elems - 1;
        acc += elem_loss(AB[2*i] * K, AB[2*i+1] * K, BA[2*i] * K, BA[2*i+1] * K,
                         BC[2*i] * K, BC[2*i+1] * K, CB[2*i] * K, CB[2*i+1] * K,
                         AC[2*i] * K, AC[2*i+1] * K, CA[2*i] * K, CA[2*i+1] * K);
    }

    // block reduction
    #pragma unroll
    for (int o = 16; o > 0; o >>= 1)
        acc += __shfl_xor_sync(0xFFFFFFFFu, acc, o);

    __shared__ float ws[NTHREADS / 32];
    if ((threadIdx.x & 31) == 0) ws[threadIdx.x >> 5] = acc;
    __syncthreads();
    if (threadIdx.x == 0) {
        float s = 0.0f;
        #pragma unroll
        for (int i = 0; i < NTHREADS / 32; i++) s += ws[i];
        g_partials[blockIdx.x] = s;
    }
}

__global__ void loss_reduce_kernel(float* __restrict__ out)
{
    __shared__ double sh[256];
    double s = 0.0;
    for (int i = threadIdx.x; i < GRID_BLOCKS; i += 256)
        s += (double)g_partials[i];
    sh[threadIdx.x] = s;
    __syncthreads();
    #pragma unroll
    for (int st = 128; st > 0; st >>= 1) {
        if (threadIdx.x < st) sh[threadIdx.x] += sh[threadIdx.x + st];
        __syncthreads();
    }
    if (threadIdx.x == 0)
        out[0] = (float)(sh[0] * 0.69314718055994530942);  // ln(2): log2 -> nat
}

extern "C" void kernel_launch(void* const* d_in, const int* in_sizes, int n_in,
                              void* d_out, int out_size)
{
    const float* AB = (const float*)d_in[0];
    const float* BA = (const float*)d_in[1];
    const float* BC = (const float*)d_in[2];
    const float* CB = (const float*)d_in[3];
    const float* AC = (const float*)d_in[4];
    const float* CA = (const float*)d_in[5];
    // d_in[6..8] (xy/yz/xz rel_id) are unused by the reference computation.

    int n_elems = in_sizes[0] / 2;

    loss_main_kernel<<<GRID_BLOCKS, NTHREADS>>>(AB, BA, BC, CB, AC, CA, n_elems);
    loss_reduce_kernel<<<1, 256>>>((float*)d_out);
}